// round 12
// baseline (speedup 1.0000x reference)
#include <cuda_runtime.h>
#include <cuda_bf16.h>
#include <cstdint>

#define LQ 512
#define LK 512
#define DD 256
#define HH1 256
#define HH2 128
#define BB 2
#define NTILES 2048      // 32 k-tiles * 32 q-tiles * 2 b
#define SGRID 148

// global scratch: projections [b][row][h_perm] (h contiguous, permuted within 16)
__device__ float g_qp[BB * LQ * HH1];
__device__ float g_kp[BB * LK * HH1];
// W2^T, bf16, [j=128][h_perm stride 272]
__device__ uint4 g_w2bt4[4352];

// perm within 16-block: orig o -> pos ((o&6)<<1) + (o&1) + ((o&8)>>2)
__device__ __forceinline__ int hperm(int h) {
    int o = h & 15;
    return (h & ~15) + ((o & 6) << 1) + (o & 1) + ((o & 8) >> 2);
}

__device__ __forceinline__ uint32_t smem_addr(const void* p) {
    return (uint32_t)__cvta_generic_to_shared(p);
}
__device__ __forceinline__ void cp_async16(uint32_t saddr, const void* gaddr) {
    asm volatile("cp.async.cg.shared.global [%0], [%1], 16;" :: "r"(saddr), "l"(gaddr));
}
#define CP_COMMIT() asm volatile("cp.async.commit_group;" ::: "memory")
#define CP_WAIT1()  asm volatile("cp.async.wait_group 1;" ::: "memory")
#define CP_WAIT0()  asm volatile("cp.async.wait_group 0;" ::: "memory")

__device__ __forceinline__ void mma_tf32(float* c, const float* a, const float* b) {
    asm volatile(
        "mma.sync.aligned.m16n8k8.row.col.f32.tf32.tf32.f32 "
        "{%0,%1,%2,%3}, {%4,%5,%6,%7}, {%8,%9}, {%0,%1,%2,%3};"
        : "+f"(c[0]), "+f"(c[1]), "+f"(c[2]), "+f"(c[3])
        : "r"(__float_as_uint(a[0])), "r"(__float_as_uint(a[1])),
          "r"(__float_as_uint(a[2])), "r"(__float_as_uint(a[3])),
          "r"(__float_as_uint(b[0])), "r"(__float_as_uint(b[1])));
}

__device__ __forceinline__ float tf32_hi(float x) {
    return __uint_as_float(__float_as_uint(x) & 0xffffe000u);
}

// ---------------------------------------------------------------------------
// Kernel 1: projections (z=0 query, z=1 key) via tf32 mma, cp.async-pipelined
// W1 chunks; z=2 slice packs W2^T bf16.
// ---------------------------------------------------------------------------
#define SXP 260
#define SWP 264
#define PM_SMEM ((16 * SXP + 2 * 64 * SWP) * 4)   // ~151.8 KB

__global__ void __launch_bounds__(512, 1)
proj_mma_kernel(const float* __restrict__ query,
                const float* __restrict__ key,
                const float* __restrict__ W1,
                const float* __restrict__ b1,
                const float* __restrict__ W2) {
    const int tid = threadIdx.x;

    if (blockIdx.z == 2) {   // merged w2bt: 64 blocks x 512 thr = 32768 elems
        int idx = (blockIdx.y * 32 + blockIdx.x) * 512 + tid;
        int j = idx & 127, h = idx >> 7;
        float v = __ldg(W2 + h * HH2 + j);
        __nv_bfloat16 bv = __float2bfloat16(v);
        ((uint16_t*)g_w2bt4)[j * 272 + hperm(h)] = *(uint16_t*)&bv;
        return;
    }

    extern __shared__ float psm[];
    float* sx = psm;                      // [16][SXP]
    float* sw1 = psm + 16 * SXP;          // [2][64][SWP]
    const uint32_t sw1a = smem_addr(sw1);

    const int row0 = blockIdx.x * 16;
    const int b = blockIdx.y;
    const int which = blockIdx.z;
    const float* W1h = W1 + (long)which * DD * HH1;

    #pragma unroll
    for (int i4 = tid; i4 < 4096; i4 += 512) {
        int dd = i4 >> 6, c = i4 & 63;
        cp_async16(sw1a + (uint32_t)(dd * SWP + c * 4) * 4, (const float4*)W1h + i4);
    }
    CP_COMMIT();

    {
        const float4* X4 = (const float4*)((which ? key : query) + ((long)b * LQ + row0) * DD);
        #pragma unroll
        for (int i4 = tid; i4 < 1024; i4 += 512) {
            int r = i4 >> 6, c = i4 & 63;
            *(float4*)(sx + r * SXP + c * 4) = __ldg(X4 + i4);
        }
    }

    const int w = tid >> 5, lane = tid & 31;
    const int lr = lane >> 2, lc = lane & 3;
    const int n0 = w * 16;

    float acc[2][4];
    #pragma unroll
    for (int nt = 0; nt < 2; nt++)
        #pragma unroll
        for (int c = 0; c < 4; c++) acc[nt][c] = 0.f;

    #pragma unroll 1
    for (int dc = 0; dc < 4; dc++) {
        const int cur = dc & 1;
        if (dc + 1 < 4) {
            const float4* src = (const float4*)(W1h + (long)(dc + 1) * 64 * HH1);
            const uint32_t dstb = sw1a + (uint32_t)((dc + 1) & 1) * (64 * SWP * 4);
            #pragma unroll
            for (int i4 = tid; i4 < 4096; i4 += 512) {
                int dd = i4 >> 6, c = i4 & 63;
                cp_async16(dstb + (uint32_t)(dd * SWP + c * 4) * 4, src + i4);
            }
            CP_COMMIT();
            CP_WAIT1();
        } else {
            CP_WAIT0();
        }
        __syncthreads();

        const float* sw = sw1 + cur * (64 * SWP);
        #pragma unroll
        for (int kc = 0; kc < 8; kc++) {
            const int kg = dc * 64 + kc * 8;
            const int kl = kc * 8;
            float a[4];
            a[0] = sx[lr * SXP + kg + lc];
            a[1] = sx[(lr + 8) * SXP + kg + lc];
            a[2] = sx[lr * SXP + kg + lc + 4];
            a[3] = sx[(lr + 8) * SXP + kg + lc + 4];
            #pragma unroll
            for (int nt = 0; nt < 2; nt++) {
                float bf[2];
                bf[0] = sw[(kl + lc) * SWP + n0 + nt * 8 + lr];
                bf[1] = sw[(kl + lc + 4) * SWP + n0 + nt * 8 + lr];
                mma_tf32(acc[nt], a, bf);
            }
        }
        __syncthreads();
    }

    float* dstb = (which ? g_kp : g_qp) + ((long)b * LQ + row0) * HH1;
    #pragma unroll
    for (int nt = 0; nt < 2; nt++) {
        const int n = n0 + nt * 8 + 2 * lc;
        const float bb0 = which ? 0.f : __ldg(b1 + n);
        const float bb1 = which ? 0.f : __ldg(b1 + n + 1);
        const int hp0 = hperm(n), hp1 = hperm(n + 1);
        dstb[(long)lr * HH1 + hp0]       = acc[nt][0] + bb0;
        dstb[(long)lr * HH1 + hp1]       = acc[nt][1] + bb1;
        dstb[(long)(lr + 8) * HH1 + hp0] = acc[nt][2] + bb0;
        dstb[(long)(lr + 8) * HH1 + hp1] = acc[nt][3] + bb1;
    }
}

// ---------------------------------------------------------------------------
// Kernel 2: PERSISTENT fused MLP score kernel (mma.sync m16n8k16 bf16).
// ---------------------------------------------------------------------------
#define OFF_W2B   0                    // bf16 [128][272] = 69632 B
#define OFF_QP0   69632                // fp32 [16][272] = 17408 B
#define OFF_KP0   87040
#define OFF_QP1   104448
#define OFF_KP1   121856
#define OFF_BWB   139264               // float2[128] = 1024 B
#define OFF_PARTB 140288               // float[512] = 2048 B
#define SMEM_BYTES 142336

__device__ __forceinline__ uint32_t pack_relu_bf16(float lo, float hi) {
    uint32_t r;
    asm("cvt.rn.bf16x2.f32 %0, %1, %2;" : "=r"(r) : "f"(hi), "f"(lo));
    asm("max.bf16x2 %0, %0, %1;" : "+r"(r) : "r"(0u));
    return r;
}

__device__ __forceinline__ void mma_bf16(float* c, const uint32_t* a, const uint32_t* b) {
    asm volatile(
        "mma.sync.aligned.m16n8k16.row.col.f32.bf16.bf16.f32 "
        "{%0,%1,%2,%3}, {%4,%5,%6,%7}, {%8,%9}, {%0,%1,%2,%3};"
        : "+f"(c[0]), "+f"(c[1]), "+f"(c[2]), "+f"(c[3])
        : "r"(a[0]), "r"(a[1]), "r"(a[2]), "r"(a[3]), "r"(b[0]), "r"(b[1]));
}

__global__ void __launch_bounds__(512, 1)
score_mma_kernel(const float* __restrict__ b2, const float* __restrict__ W3,
                 const float* __restrict__ b3, float* __restrict__ scores) {
    extern __shared__ char smem[];
    float* smemf = (float*)smem;
    const int tid = threadIdx.x;
    const uint32_t sbase = smem_addr(smem);

    {
        const int t0 = blockIdx.x;
        const int kb = t0 & 31, qb = (t0 >> 5) & 31, b = t0 >> 10;
        const float4* gq = (const float4*)(g_qp + ((long)b * LQ + qb * 16) * HH1);
        const float4* gk = (const float4*)(g_kp + ((long)b * LK + kb * 16) * HH1);
        #pragma unroll
        for (int i4 = tid; i4 < 1024; i4 += 512) {
            int r = i4 >> 6, c = i4 & 63;
            uint32_t off = (uint32_t)(r * 68 + c) * 16;
            cp_async16(sbase + OFF_QP0 + off, gq + i4);
            cp_async16(sbase + OFF_KP0 + off, gk + i4);
        }
        CP_COMMIT();
    }

    {
        uint4* dW = (uint4*)(smem + OFF_W2B);
        #pragma unroll 4
        for (int i = tid; i < 4352; i += 512) dW[i] = g_w2bt4[i];
        if (tid < HH2)
            ((float2*)(smem + OFF_BWB))[tid] = make_float2(__ldg(b2 + tid), __ldg(W3 + tid));
    }

    const int w = tid >> 5, lane = tid & 31;
    const int mwarp = w & 7;
    const int nwarp = w >> 3;
    const int n0 = nwarp * 64;
    const int lr = lane >> 2, lc = lane & 3;
    const uint16_t* w2p = (const uint16_t*)(smem + OFF_W2B) + (n0 + lr) * 272 + 4 * lc;
    const float2* bw = (const float2*)(smem + OFF_BWB);
    float* part = smemf + OFF_PARTB / 4;
    const float bb3 = __ldg(b3);

    int it = 0;
    #pragma unroll 1
    for (int t = blockIdx.x; t < NTILES; t += SGRID, it++) {
        const int cur = it & 1;
        const int qoff = cur ? OFF_QP1 : OFF_QP0;
        const int koff = cur ? OFF_KP1 : OFF_KP0;

        const int t2 = t + SGRID;
        if (t2 < NTILES) {
            const int kb2 = t2 & 31, qb2 = (t2 >> 5) & 31, b2i = t2 >> 10;
            const float4* gq = (const float4*)(g_qp + ((long)b2i * LQ + qb2 * 16) * HH1);
            const float4* gk = (const float4*)(g_kp + ((long)b2i * LK + kb2 * 16) * HH1);
            const int qo2 = cur ? OFF_QP0 : OFF_QP1;
            const int ko2 = cur ? OFF_KP0 : OFF_KP1;
            #pragma unroll
            for (int i4 = tid; i4 < 1024; i4 += 512) {
                int r = i4 >> 6, c = i4 & 63;
                uint32_t off = (uint32_t)(r * 68 + c) * 16;
                cp_async16(sbase + qo2 + off, gq + i4);
                cp_async16(sbase + ko2 + off, gk + i4);
            }
            CP_COMMIT();
            CP_WAIT1();
        } else {
            CP_WAIT0();
        }
        __syncthreads();

        const int kb = t & 31, qb = (t >> 5) & 31, b = t >> 10;

        float acc[2][8][4];
        #pragma unroll
        for (int mt = 0; mt < 2; mt++)
            #pragma unroll
            for (int nt = 0; nt < 8; nt++)
                #pragma unroll
                for (int c = 0; c < 4; c++) acc[mt][nt][c] = 0.f;

        const float* kpA = smemf + koff / 4 + lr * 272 + 4 * lc;
        const float* kpB = kpA + 8 * 272;
        const float* qpb = smemf + qoff / 4 + (mwarp * 2) * 272 + 4 * lc;

        #pragma unroll 4
        for (int c = 0; c < 16; c++) {
            const int hb = c * 16;
            const float4 kA = *(const float4*)(kpA + hb);
            const float4 kB = *(const float4*)(kpB + hb);
            uint2 bfr[8];
            #pragma unroll
            for (int nt = 0; nt < 8; nt++)
                bfr[nt] = *(const uint2*)(w2p + nt * (8 * 272) + hb);

            #pragma unroll
            for (int mt = 0; mt < 2; mt++) {
                const float4 q4 = *(const float4*)(qpb + mt * 272 + hb);
                uint32_t a[4];
                a[0] = pack_relu_bf16(q4.x + kA.x, q4.y + kA.y);
                a[1] = pack_relu_bf16(q4.x + kB.x, q4.y + kB.y);
                a[2] = pack_relu_bf16(q4.z + kA.z, q4.w + kA.w);
                a[3] = pack_relu_bf16(q4.z + kB.z, q4.w + kB.w);
                #pragma unroll
                for (int nt = 0; nt < 8; nt++)
                    mma_bf16(acc[mt][nt], a, (const uint32_t*)&bfr[nt]);
            }
        }

        float s0[2], s1[2];
        #pragma unroll
        for (int mt = 0; mt < 2; mt++) {
            float t0 = 0.f, t1 = 0.f;
            #pragma unroll
            for (int nt = 0; nt < 8; nt++) {
                const int jj = n0 + nt * 8 + 2 * lc;
                float2 cA = bw[jj];
                float2 cB = bw[jj + 1];
                t0 = fmaf(fmaxf(acc[mt][nt][0] + cA.x, 0.f), cA.y, t0);
                t0 = fmaf(fmaxf(acc[mt][nt][1] + cB.x, 0.f), cB.y, t0);
                t1 = fmaf(fmaxf(acc[mt][nt][2] + cA.x, 0.f), cA.y, t1);
                t1 = fmaf(fmaxf(acc[mt][nt][3] + cB.x, 0.f), cB.y, t1);
            }
            s0[mt] = t0; s1[mt] = t1;
        }
        #pragma unroll
        for (int off = 1; off < 4; off <<= 1)
            #pragma unroll
            for (int mt = 0; mt < 2; mt++) {
                s0[mt] += __shfl_xor_sync(0xffffffffu, s0[mt], off);
                s1[mt] += __shfl_xor_sync(0xffffffffu, s1[mt], off);
            }

        if (lc == 0) {
            #pragma unroll
            for (int mt = 0; mt < 2; mt++) {
                part[nwarp * 256 + (mwarp * 2 + mt) * 16 + lr]     = s0[mt];
                part[nwarp * 256 + (mwarp * 2 + mt) * 16 + lr + 8] = s1[mt];
            }
        }
        __syncthreads();
        if (tid < 256) {
            const int p = tid;
            float f = part[p] + part[256 + p] + bb3;
            const int q = qb * 16 + (p >> 4);
            scores[((long)b * LQ + q) * LK + kb * 16 + (p & 15)] = f;
        }
    }
}

// ---------------------------------------------------------------------------
// Kernel 3: FUSED softmax + AV (3xtf32 split-precision mma).
// Block = (16 q rows, 128-d half, b).  256 threads / 8 warps.
// ---------------------------------------------------------------------------
#define SA_STR 516                      // attn smem stride (floats)
#define SV_STR 136                      // V smem stride (floats)
#define FOFF_V  (16 * SA_STR)
#define F_SMEM_FLOATS (16 * SA_STR + 3 * 64 * SV_STR)
#define F_SMEM_BYTES (F_SMEM_FLOATS * 4)   // 137600 B

__global__ void __launch_bounds__(256, 1)
fused_softmax_av_kernel(const float* __restrict__ value,
                        const int* __restrict__ mask,
                        float* __restrict__ out,
                        float* __restrict__ attn) {
    extern __shared__ float fsm[];
    float* sa = fsm;                    // [16][SA_STR]
    float* sv = fsm + FOFF_V;           // [3][64][SV_STR]
    const uint32_t sva = smem_addr(sv);

    const int tid = threadIdx.x;
    const int w = tid >> 5, lane = tid & 31;
    const int qt = blockIdx.x;
    const int dh = blockIdx.y;
    const int b = blockIdx.z;
    const int q0 = qt * 16;

    const float* Vb = value + (long)b * LK * DD + dh * 128;

    // pre-issue V chunks 0,1
    #pragma unroll
    for (int cpre = 0; cpre < 2; cpre++) {
        #pragma unroll
        for (int i4 = tid; i4 < 2048; i4 += 256) {
            int r = i4 >> 5, cc = i4 & 31;
            cp_async16(sva + (uint32_t)(cpre * 64 * SV_STR + r * SV_STR + cc * 4) * 4,
                       (const float4*)(Vb + (long)(cpre * 64 + r) * DD) + cc);
        }
        CP_COMMIT();
    }

    // ---- phase 1: softmax, 2 rows per warp; lane owns k in [lane*16, lane*16+16) ----
    #pragma unroll
    for (int rr = 0; rr < 2; rr++) {
        const int r = w * 2 + rr;
        const long rowbase = ((long)b * LQ + q0 + r) * LK;
        const float4* s4p = (const float4*)(attn + rowbase + lane * 16);
        const int4* m4p = (const int4*)(mask + rowbase + lane * 16);

        float vals[16];
        float mx = -3.4e38f;
        #pragma unroll
        for (int i4 = 0; i4 < 4; i4++) {
            float4 s4 = s4p[i4];
            int4 m4 = __ldg(m4p + i4);
            vals[i4 * 4 + 0] = m4.x ? s4.x : -1e9f;
            vals[i4 * 4 + 1] = m4.y ? s4.y : -1e9f;
            vals[i4 * 4 + 2] = m4.z ? s4.z : -1e9f;
            vals[i4 * 4 + 3] = m4.w ? s4.w : -1e9f;
        }
        #pragma unroll
        for (int i = 0; i < 16; i++) mx = fmaxf(mx, vals[i]);
        #pragma unroll
        for (int off = 16; off > 0; off >>= 1)
            mx = fmaxf(mx, __shfl_xor_sync(0xffffffffu, mx, off));

        float sum = 0.f;
        #pragma unroll
        for (int i = 0; i < 16; i++) {
            vals[i] = __expf(vals[i] - mx);
            sum += vals[i];
        }
        #pragma unroll
        for (int off = 16; off > 0; off >>= 1)
            sum += __shfl_xor_sync(0xffffffffu, sum, off);
        const float inv = 1.f / sum;

        float* sar = sa + r * SA_STR + lane * 16;
        float4* adst = (float4*)(attn + rowbase + lane * 16);
        #pragma unroll
        for (int i4 = 0; i4 < 4; i4++) {
            float4 o;
            o.x = vals[i4 * 4 + 0] * inv;
            o.y = vals[i4 * 4 + 1] * inv;
            o.z = vals[i4 * 4 + 2] * inv;
            o.w = vals[i4 * 4 + 3] * inv;
            *(float4*)(sar + i4 * 4) = o;
            if (dh == 0) adst[i4] = o;
        }
    }

    // ---- phase 2: 3xtf32 mma AV ----
    const int lr = lane >> 2, lc = lane & 3;
    const int n0 = w * 16;

    float acc[2][4];
    #pragma unroll
    for (int nt = 0; nt < 2; nt++)
        #pragma unroll
        for (int c = 0; c < 4; c++) acc[nt][c] = 0.f;

    #pragma unroll 1
    for (int c = 0; c < 8; c++) {
        if (c < 7) { CP_WAIT1(); } else { CP_WAIT0(); }
        __syncthreads();

        if (c + 2 < 8) {
            const int buf = (c + 2) % 3;
            #pragma unroll
            for (int i4 = tid; i4 < 2048; i4 += 256) {
                int r = i4 >> 5, cc = i4 & 31;
                cp_async16(sva + (uint32_t)(buf * 64 * SV_STR + r * SV_STR + cc * 4) * 4,
                           (const float4*)(Vb + (long)((c + 2) * 64 + r) * DD) + cc);
            }
            CP_COMMIT();
        }

        const float* svc = sv + (c % 3) * (64 * SV_STR);
        const int kg = c * 64;
        #pragma unroll
        for (int ks = 0; ks < 8; ks++) {
            const int k0 = ks * 8;
            float a[4], ah[4], al[4];
            a[0] = sa[lr * SA_STR + kg + k0 + lc];
            a[1] = sa[(lr + 8) * SA_STR + kg + k0 + lc];
            a[2] = sa[lr * SA_STR + kg + k0 + lc + 4];
            a[3] = sa[(lr + 8) * SA_STR + kg + k0 + lc + 4];
            #pragma unroll
            for (int i = 0; i < 4; i++) {
                ah[i] = tf32_hi(a[i]);
                al[i] = a[i] - ah[i];
            }
            #pragma unroll
            for (int nt = 0; nt < 2; nt++) {
                float bf[2], bh[2], bl[2];
                bf[0] = svc[(k0 + lc) * SV_STR + n0 + nt * 8 + lr];
                bf[1] = svc[(k0 + lc + 4) * SV_STR + n0 + nt * 8 + lr];
                bh[0] = tf32_hi(bf[0]); bl[0] = bf[0] - bh[0];
                bh[1] = tf32_hi(bf[1]); bl[1] = bf[1] - bh[1];
                mma_tf32(acc[nt], ah, bh);
                mma_tf32(acc[nt], al, bh);
                mma_tf32(acc[nt], ah, bl);
            }
        }
    }

    #pragma unroll
    for (int nt = 0; nt < 2; nt++) {
        const int col = dh * 128 + n0 + nt * 8 + 2 * lc;
        float* o0 = out + ((long)b * LQ + q0 + lr) * DD + col;
        float* o1 = out + ((long)b * LQ + q0 + lr + 8) * DD + col;
        *(float2*)o0 = make_float2(acc[nt][0], acc[nt][1]);
        *(float2*)o1 = make_float2(acc[nt][2], acc[nt][3]);
    }
}

// ---------------------------------------------------------------------------
extern "C" void kernel_launch(void* const* d_in, const int* in_sizes, int n_in,
                              void* d_out, int out_size) {
    const float* query = (const float*)d_in[0];
    const float* key   = (const float*)d_in[1];
    const float* value = (const float*)d_in[2];
    const int*   mask  = (const int*)d_in[3];
    const float* W1 = (const float*)d_in[4];
    const float* b1 = (const float*)d_in[5];
    const float* W2 = (const float*)d_in[6];
    const float* b2 = (const float*)d_in[7];
    const float* W3 = (const float*)d_in[8];
    const float* b3 = (const float*)d_in[9];

    float* out  = (float*)d_out;                 // [B, LQ, D]
    float* attn = out + (long)BB * LQ * DD;      // [B, LQ, LK]

    cudaFuncSetAttribute(proj_mma_kernel,
                         cudaFuncAttributeMaxDynamicSharedMemorySize, PM_SMEM);
    cudaFuncSetAttribute(score_mma_kernel,
                         cudaFuncAttributeMaxDynamicSharedMemorySize, SMEM_BYTES);
    cudaFuncSetAttribute(fused_softmax_av_kernel,
                         cudaFuncAttributeMaxDynamicSharedMemorySize, F_SMEM_BYTES);

    proj_mma_kernel<<<dim3(LQ / 16, BB, 3), 512, PM_SMEM>>>(query, key, W1, b1, W2);
    score_mma_kernel<<<SGRID, 512, SMEM_BYTES>>>(b2, W3, b3, attn);
    fused_softmax_av_kernel<<<dim3(LQ / 16, 2, BB), 256, F_SMEM_BYTES>>>(value, mask, out, attn);
}

// round 13
// speedup vs baseline: 1.1051x; 1.1051x over previous
#include <cuda_runtime.h>
#include <cuda_bf16.h>
#include <cstdint>

#define LQ 512
#define LK 512
#define DD 256
#define HH1 256
#define HH2 128
#define BB 2
#define NTILES 2048      // 32 k-tiles * 32 q-tiles * 2 b
#define SGRID 148

// global scratch: projections as bf16x2, [b][row][h_perm/2]
__device__ uint32_t g_qpb[BB * LQ * HH1 / 2];
__device__ uint32_t g_kpb[BB * LK * HH1 / 2];
// W2^T, bf16, [j=128][h_perm stride 272]
__device__ uint4 g_w2bt4[4352];

// perm within 16-block: orig o -> pos ((o&6)<<1) + (o&1) + ((o&8)>>2)
__device__ __forceinline__ int hperm(int h) {
    int o = h & 15;
    return (h & ~15) + ((o & 6) << 1) + (o & 1) + ((o & 8) >> 2);
}

__device__ __forceinline__ uint32_t smem_addr(const void* p) {
    return (uint32_t)__cvta_generic_to_shared(p);
}
__device__ __forceinline__ void cp_async16(uint32_t saddr, const void* gaddr) {
    asm volatile("cp.async.cg.shared.global [%0], [%1], 16;" :: "r"(saddr), "l"(gaddr));
}
#define CP_COMMIT() asm volatile("cp.async.commit_group;" ::: "memory")
#define CP_WAIT1()  asm volatile("cp.async.wait_group 1;" ::: "memory")
#define CP_WAIT0()  asm volatile("cp.async.wait_group 0;" ::: "memory")

__device__ __forceinline__ void mma_tf32(float* c, const float* a, const float* b) {
    asm volatile(
        "mma.sync.aligned.m16n8k8.row.col.f32.tf32.tf32.f32 "
        "{%0,%1,%2,%3}, {%4,%5,%6,%7}, {%8,%9}, {%0,%1,%2,%3};"
        : "+f"(c[0]), "+f"(c[1]), "+f"(c[2]), "+f"(c[3])
        : "r"(__float_as_uint(a[0])), "r"(__float_as_uint(a[1])),
          "r"(__float_as_uint(a[2])), "r"(__float_as_uint(a[3])),
          "r"(__float_as_uint(b[0])), "r"(__float_as_uint(b[1])));
}

__device__ __forceinline__ float tf32_hi(float x) {
    return __uint_as_float(__float_as_uint(x) & 0xffffe000u);
}

__device__ __forceinline__ uint32_t pack_bf16x2(float lo, float hi) {
    uint32_t r;
    asm("cvt.rn.bf16x2.f32 %0, %1, %2;" : "=r"(r) : "f"(hi), "f"(lo));
    return r;
}
// relu(x + y) on bf16x2 pairs
__device__ __forceinline__ uint32_t hadd_relu(uint32_t x, uint32_t y) {
    uint32_t r;
    asm("add.rn.bf16x2 %0, %1, %2;" : "=r"(r) : "r"(x), "r"(y));
    asm("max.bf16x2 %0, %0, %1;" : "+r"(r) : "r"(0u));
    return r;
}

// ---------------------------------------------------------------------------
// Kernel 1: projections (z=0 query, z=1 key) via tf32 mma, cp.async-pipelined
// W1 chunks; z=2 slice packs W2^T bf16.  Output stored as bf16x2 (permuted h).
// ---------------------------------------------------------------------------
#define SXP 260
#define SWP 264
#define PM_SMEM ((16 * SXP + 2 * 64 * SWP) * 4)   // ~151.8 KB

__global__ void __launch_bounds__(512, 1)
proj_mma_kernel(const float* __restrict__ query,
                const float* __restrict__ key,
                const float* __restrict__ W1,
                const float* __restrict__ b1,
                const float* __restrict__ W2) {
    const int tid = threadIdx.x;

    if (blockIdx.z == 2) {   // merged w2bt: 64 blocks x 512 thr = 32768 elems
        int idx = (blockIdx.y * 32 + blockIdx.x) * 512 + tid;
        int j = idx & 127, h = idx >> 7;
        float v = __ldg(W2 + h * HH2 + j);
        __nv_bfloat16 bv = __float2bfloat16(v);
        ((uint16_t*)g_w2bt4)[j * 272 + hperm(h)] = *(uint16_t*)&bv;
        return;
    }

    extern __shared__ float psm[];
    float* sx = psm;                      // [16][SXP]
    float* sw1 = psm + 16 * SXP;          // [2][64][SWP]
    const uint32_t sw1a = smem_addr(sw1);

    const int row0 = blockIdx.x * 16;
    const int b = blockIdx.y;
    const int which = blockIdx.z;
    const float* W1h = W1 + (long)which * DD * HH1;

    #pragma unroll
    for (int i4 = tid; i4 < 4096; i4 += 512) {
        int dd = i4 >> 6, c = i4 & 63;
        cp_async16(sw1a + (uint32_t)(dd * SWP + c * 4) * 4, (const float4*)W1h + i4);
    }
    CP_COMMIT();

    {
        const float4* X4 = (const float4*)((which ? key : query) + ((long)b * LQ + row0) * DD);
        #pragma unroll
        for (int i4 = tid; i4 < 1024; i4 += 512) {
            int r = i4 >> 6, c = i4 & 63;
            *(float4*)(sx + r * SXP + c * 4) = __ldg(X4 + i4);
        }
    }

    const int w = tid >> 5, lane = tid & 31;
    const int lr = lane >> 2, lc = lane & 3;
    const int n0 = w * 16;

    float acc[2][4];
    #pragma unroll
    for (int nt = 0; nt < 2; nt++)
        #pragma unroll
        for (int c = 0; c < 4; c++) acc[nt][c] = 0.f;

    #pragma unroll 1
    for (int dc = 0; dc < 4; dc++) {
        const int cur = dc & 1;
        if (dc + 1 < 4) {
            const float4* src = (const float4*)(W1h + (long)(dc + 1) * 64 * HH1);
            const uint32_t dstb = sw1a + (uint32_t)((dc + 1) & 1) * (64 * SWP * 4);
            #pragma unroll
            for (int i4 = tid; i4 < 4096; i4 += 512) {
                int dd = i4 >> 6, c = i4 & 63;
                cp_async16(dstb + (uint32_t)(dd * SWP + c * 4) * 4, src + i4);
            }
            CP_COMMIT();
            CP_WAIT1();
        } else {
            CP_WAIT0();
        }
        __syncthreads();

        const float* sw = sw1 + cur * (64 * SWP);
        #pragma unroll
        for (int kc = 0; kc < 8; kc++) {
            const int kg = dc * 64 + kc * 8;
            const int kl = kc * 8;
            float a[4];
            a[0] = sx[lr * SXP + kg + lc];
            a[1] = sx[(lr + 8) * SXP + kg + lc];
            a[2] = sx[lr * SXP + kg + lc + 4];
            a[3] = sx[(lr + 8) * SXP + kg + lc + 4];
            #pragma unroll
            for (int nt = 0; nt < 2; nt++) {
                float bf[2];
                bf[0] = sw[(kl + lc) * SWP + n0 + nt * 8 + lr];
                bf[1] = sw[(kl + lc + 4) * SWP + n0 + nt * 8 + lr];
                mma_tf32(acc[nt], a, bf);
            }
        }
        __syncthreads();
    }

    // epilogue: add b1 (q only), pack bf16x2, write permuted h
    uint32_t* dstb = (which ? g_kpb : g_qpb) + ((long)b * LQ + row0) * (HH1 / 2);
    #pragma unroll
    for (int nt = 0; nt < 2; nt++) {
        const int n = n0 + nt * 8 + 2 * lc;
        const float bb0 = which ? 0.f : __ldg(b1 + n);
        const float bb1 = which ? 0.f : __ldg(b1 + n + 1);
        const int hp = hperm(n) >> 1;    // hperm(n) even, hperm(n+1)=hperm(n)+1
        dstb[(long)lr * (HH1 / 2) + hp] =
            pack_bf16x2(acc[nt][0] + bb0, acc[nt][1] + bb1);
        dstb[(long)(lr + 8) * (HH1 / 2) + hp] =
            pack_bf16x2(acc[nt][2] + bb0, acc[nt][3] + bb1);
    }
}

// ---------------------------------------------------------------------------
// Kernel 2: PERSISTENT fused MLP score kernel (mma.sync m16n8k16 bf16).
// qp/kp now bf16 in smem: stride 272 bf16 (544 B).
// ---------------------------------------------------------------------------
#define OFF_W2B   0                    // bf16 [128][272] = 69632 B
#define OFF_QP0   69632                // bf16 [16][272] = 8704 B
#define OFF_KP0   78336
#define OFF_QP1   87040
#define OFF_KP1   95744
#define OFF_BWB   104448               // float2[128] = 1024 B
#define OFF_PARTB 105472               // float[512] = 2048 B
#define SMEM_BYTES 107520

__device__ __forceinline__ void mma_bf16(float* c, const uint32_t* a, const uint32_t* b) {
    asm volatile(
        "mma.sync.aligned.m16n8k16.row.col.f32.bf16.bf16.f32 "
        "{%0,%1,%2,%3}, {%4,%5,%6,%7}, {%8,%9}, {%0,%1,%2,%3};"
        : "+f"(c[0]), "+f"(c[1]), "+f"(c[2]), "+f"(c[3])
        : "r"(a[0]), "r"(a[1]), "r"(a[2]), "r"(a[3]), "r"(b[0]), "r"(b[1]));
}

__global__ void __launch_bounds__(512, 1)
score_mma_kernel(const float* __restrict__ b2, const float* __restrict__ W3,
                 const float* __restrict__ b3, float* __restrict__ scores) {
    extern __shared__ char smem[];
    float* smemf = (float*)smem;
    const int tid = threadIdx.x;
    const uint32_t sbase = smem_addr(smem);

    // prefetch first tile's qp/kp (bf16: 16 rows x 32 x 16B chunks each)
    {
        const int t0 = blockIdx.x;
        const int kb = t0 & 31, qb = (t0 >> 5) & 31, b = t0 >> 10;
        const uint4* gq = (const uint4*)(g_qpb + ((long)b * LQ + qb * 16) * (HH1 / 2));
        const uint4* gk = (const uint4*)(g_kpb + ((long)b * LK + kb * 16) * (HH1 / 2));
        {
            int r = tid >> 5, c = tid & 31;           // 512 chunks q
            cp_async16(sbase + OFF_QP0 + (uint32_t)(r * 544 + c * 16), gq + r * 32 + c);
            cp_async16(sbase + OFF_KP0 + (uint32_t)(r * 544 + c * 16), gk + r * 32 + c);
        }
        CP_COMMIT();
    }

    // stage W2 + b2/W3 once
    {
        uint4* dW = (uint4*)(smem + OFF_W2B);
        #pragma unroll 4
        for (int i = tid; i < 4352; i += 512) dW[i] = g_w2bt4[i];
        if (tid < HH2)
            ((float2*)(smem + OFF_BWB))[tid] = make_float2(__ldg(b2 + tid), __ldg(W3 + tid));
    }

    const int w = tid >> 5, lane = tid & 31;
    const int mwarp = w & 7;
    const int nwarp = w >> 3;
    const int n0 = nwarp * 64;
    const int lr = lane >> 2, lc = lane & 3;
    const uint16_t* w2p = (const uint16_t*)(smem + OFF_W2B) + (n0 + lr) * 272 + 4 * lc;
    const float2* bw = (const float2*)(smem + OFF_BWB);
    float* part = smemf + OFF_PARTB / 4;
    const float bb3 = __ldg(b3);

    int it = 0;
    #pragma unroll 1
    for (int t = blockIdx.x; t < NTILES; t += SGRID, it++) {
        const int cur = it & 1;
        const int qoff = cur ? OFF_QP1 : OFF_QP0;
        const int koff = cur ? OFF_KP1 : OFF_KP0;

        const int t2 = t + SGRID;
        if (t2 < NTILES) {
            const int kb2 = t2 & 31, qb2 = (t2 >> 5) & 31, b2i = t2 >> 10;
            const uint4* gq = (const uint4*)(g_qpb + ((long)b2i * LQ + qb2 * 16) * (HH1 / 2));
            const uint4* gk = (const uint4*)(g_kpb + ((long)b2i * LK + kb2 * 16) * (HH1 / 2));
            const int qo2 = cur ? OFF_QP0 : OFF_QP1;
            const int ko2 = cur ? OFF_KP0 : OFF_KP1;
            {
                int r = tid >> 5, c = tid & 31;
                cp_async16(sbase + qo2 + (uint32_t)(r * 544 + c * 16), gq + r * 32 + c);
                cp_async16(sbase + ko2 + (uint32_t)(r * 544 + c * 16), gk + r * 32 + c);
            }
            CP_COMMIT();
            CP_WAIT1();
        } else {
            CP_WAIT0();
        }
        __syncthreads();

        const int kb = t & 31, qb = (t >> 5) & 31, b = t >> 10;

        float acc[2][8][4];
        #pragma unroll
        for (int mt = 0; mt < 2; mt++)
            #pragma unroll
            for (int nt = 0; nt < 8; nt++)
                #pragma unroll
                for (int c = 0; c < 4; c++) acc[mt][nt][c] = 0.f;

        const uint16_t* kpA = (const uint16_t*)(smem + koff) + lr * 272 + 4 * lc;
        const uint16_t* kpB = kpA + 8 * 272;
        const uint16_t* qpp = (const uint16_t*)(smem + qoff) + (mwarp * 2) * 272 + 4 * lc;

        #pragma unroll 4
        for (int c = 0; c < 16; c++) {
            const int he = c * 16;                    // element offset of chunk
            const uint2 kAu = *(const uint2*)(kpA + he);
            const uint2 kBu = *(const uint2*)(kpB + he);
            uint2 bfr[8];
            #pragma unroll
            for (int nt = 0; nt < 8; nt++)
                bfr[nt] = *(const uint2*)(w2p + nt * (8 * 272) + he);

            #pragma unroll
            for (int mt = 0; mt < 2; mt++) {
                const uint2 qu = *(const uint2*)(qpp + mt * 272 + he);
                uint32_t a[4];
                a[0] = hadd_relu(qu.x, kAu.x);   // rows lr,   k 2lc..2lc+1
                a[1] = hadd_relu(qu.x, kBu.x);   // rows lr+8, k 2lc..2lc+1
                a[2] = hadd_relu(qu.y, kAu.y);   // rows lr,   k 2lc+8..9
                a[3] = hadd_relu(qu.y, kBu.y);   // rows lr+8, k 2lc+8..9
                #pragma unroll
                for (int nt = 0; nt < 8; nt++)
                    mma_bf16(acc[mt][nt], a, (const uint32_t*)&bfr[nt]);
            }
        }

        float s0[2], s1[2];
        #pragma unroll
        for (int mt = 0; mt < 2; mt++) {
            float t0 = 0.f, t1 = 0.f;
            #pragma unroll
            for (int nt = 0; nt < 8; nt++) {
                const int jj = n0 + nt * 8 + 2 * lc;
                float2 cA = bw[jj];
                float2 cB = bw[jj + 1];
                t0 = fmaf(fmaxf(acc[mt][nt][0] + cA.x, 0.f), cA.y, t0);
                t0 = fmaf(fmaxf(acc[mt][nt][1] + cB.x, 0.f), cB.y, t0);
                t1 = fmaf(fmaxf(acc[mt][nt][2] + cA.x, 0.f), cA.y, t1);
                t1 = fmaf(fmaxf(acc[mt][nt][3] + cB.x, 0.f), cB.y, t1);
            }
            s0[mt] = t0; s1[mt] = t1;
        }
        #pragma unroll
        for (int off = 1; off < 4; off <<= 1)
            #pragma unroll
            for (int mt = 0; mt < 2; mt++) {
                s0[mt] += __shfl_xor_sync(0xffffffffu, s0[mt], off);
                s1[mt] += __shfl_xor_sync(0xffffffffu, s1[mt], off);
            }

        if (lc == 0) {
            #pragma unroll
            for (int mt = 0; mt < 2; mt++) {
                part[nwarp * 256 + (mwarp * 2 + mt) * 16 + lr]     = s0[mt];
                part[nwarp * 256 + (mwarp * 2 + mt) * 16 + lr + 8] = s1[mt];
            }
        }
        __syncthreads();
        if (tid < 256) {
            const int p = tid;
            float f = part[p] + part[256 + p] + bb3;
            const int q = qb * 16 + (p >> 4);
            scores[((long)b * LQ + q) * LK + kb * 16 + (p & 15)] = f;
        }
    }
}

// ---------------------------------------------------------------------------
// Kernel 3: FUSED softmax + AV (3xtf32 split-precision mma).  (unchanged)
// ---------------------------------------------------------------------------
#define SA_STR 516
#define SV_STR 136
#define FOFF_V  (16 * SA_STR)
#define F_SMEM_FLOATS (16 * SA_STR + 3 * 64 * SV_STR)
#define F_SMEM_BYTES (F_SMEM_FLOATS * 4)   // 137600 B

__global__ void __launch_bounds__(256, 1)
fused_softmax_av_kernel(const float* __restrict__ value,
                        const int* __restrict__ mask,
                        float* __restrict__ out,
                        float* __restrict__ attn) {
    extern __shared__ float fsm[];
    float* sa = fsm;
    float* sv = fsm + FOFF_V;
    const uint32_t sva = smem_addr(sv);

    const int tid = threadIdx.x;
    const int w = tid >> 5, lane = tid & 31;
    const int qt = blockIdx.x;
    const int dh = blockIdx.y;
    const int b = blockIdx.z;
    const int q0 = qt * 16;

    const float* Vb = value + (long)b * LK * DD + dh * 128;

    #pragma unroll
    for (int cpre = 0; cpre < 2; cpre++) {
        #pragma unroll
        for (int i4 = tid; i4 < 2048; i4 += 256) {
            int r = i4 >> 5, cc = i4 & 31;
            cp_async16(sva + (uint32_t)(cpre * 64 * SV_STR + r * SV_STR + cc * 4) * 4,
                       (const float4*)(Vb + (long)(cpre * 64 + r) * DD) + cc);
        }
        CP_COMMIT();
    }

    #pragma unroll
    for (int rr = 0; rr < 2; rr++) {
        const int r = w * 2 + rr;
        const long rowbase = ((long)b * LQ + q0 + r) * LK;
        const float4* s4p = (const float4*)(attn + rowbase + lane * 16);
        const int4* m4p = (const int4*)(mask + rowbase + lane * 16);

        float vals[16];
        float mx = -3.4e38f;
        #pragma unroll
        for (int i4 = 0; i4 < 4; i4++) {
            float4 s4 = s4p[i4];
            int4 m4 = __ldg(m4p + i4);
            vals[i4 * 4 + 0] = m4.x ? s4.x : -1e9f;
            vals[i4 * 4 + 1] = m4.y ? s4.y : -1e9f;
            vals[i4 * 4 + 2] = m4.z ? s4.z : -1e9f;
            vals[i4 * 4 + 3] = m4.w ? s4.w : -1e9f;
        }
        #pragma unroll
        for (int i = 0; i < 16; i++) mx = fmaxf(mx, vals[i]);
        #pragma unroll
        for (int off = 16; off > 0; off >>= 1)
            mx = fmaxf(mx, __shfl_xor_sync(0xffffffffu, mx, off));

        float sum = 0.f;
        #pragma unroll
        for (int i = 0; i < 16; i++) {
            vals[i] = __expf(vals[i] - mx);
            sum += vals[i];
        }
        #pragma unroll
        for (int off = 16; off > 0; off >>= 1)
            sum += __shfl_xor_sync(0xffffffffu, sum, off);
        const float inv = 1.f / sum;

        float* sar = sa + r * SA_STR + lane * 16;
        float4* adst = (float4*)(attn + rowbase + lane * 16);
        #pragma unroll
        for (int i4 = 0; i4 < 4; i4++) {
            float4 o;
            o.x = vals[i4 * 4 + 0] * inv;
            o.y = vals[i4 * 4 + 1] * inv;
            o.z = vals[i4 * 4 + 2] * inv;
            o.w = vals[i4 * 4 + 3] * inv;
            *(float4*)(sar + i4 * 4) = o;
            if (dh == 0) adst[i4] = o;
        }
    }

    const int lr = lane >> 2, lc = lane & 3;
    const int n0 = w * 16;

    float acc[2][4];
    #pragma unroll
    for (int nt = 0; nt < 2; nt++)
        #pragma unroll
        for (int c = 0; c < 4; c++) acc[nt][c] = 0.f;

    #pragma unroll 1
    for (int c = 0; c < 8; c++) {
        if (c < 7) { CP_WAIT1(); } else { CP_WAIT0(); }
        __syncthreads();

        if (c + 2 < 8) {
            const int buf = (c + 2) % 3;
            #pragma unroll
            for (int i4 = tid; i4 < 2048; i4 += 256) {
                int r = i4 >> 5, cc = i4 & 31;
                cp_async16(sva + (uint32_t)(buf * 64 * SV_STR + r * SV_STR + cc * 4) * 4,
                           (const float4*)(Vb + (long)((c + 2) * 64 + r) * DD) + cc);
            }
            CP_COMMIT();
        }

        const float* svc = sv + (c % 3) * (64 * SV_STR);
        const int kg = c * 64;
        #pragma unroll
        for (int ks = 0; ks < 8; ks++) {
            const int k0 = ks * 8;
            float a[4], ah[4], al[4];
            a[0] = sa[lr * SA_STR + kg + k0 + lc];
            a[1] = sa[(lr + 8) * SA_STR + kg + k0 + lc];
            a[2] = sa[lr * SA_STR + kg + k0 + lc + 4];
            a[3] = sa[(lr + 8) * SA_STR + kg + k0 + lc + 4];
            #pragma unroll
            for (int i = 0; i < 4; i++) {
                ah[i] = tf32_hi(a[i]);
                al[i] = a[i] - ah[i];
            }
            #pragma unroll
            for (int nt = 0; nt < 2; nt++) {
                float bf[2], bh[2], bl[2];
                bf[0] = svc[(k0 + lc) * SV_STR + n0 + nt * 8 + lr];
                bf[1] = svc[(k0 + lc + 4) * SV_STR + n0 + nt * 8 + lr];
                bh[0] = tf32_hi(bf[0]); bl[0] = bf[0] - bh[0];
                bh[1] = tf32_hi(bf[1]); bl[1] = bf[1] - bh[1];
                mma_tf32(acc[nt], ah, bh);
                mma_tf32(acc[nt], al, bh);
                mma_tf32(acc[nt], ah, bl);
            }
        }
    }

    #pragma unroll
    for (int nt = 0; nt < 2; nt++) {
        const int col = dh * 128 + n0 + nt * 8 + 2 * lc;
        float* o0 = out + ((long)b * LQ + q0 + lr) * DD + col;
        float* o1 = out + ((long)b * LQ + q0 + lr + 8) * DD + col;
        *(float2*)o0 = make_float2(acc[nt][0], acc[nt][1]);
        *(float2*)o1 = make_float2(acc[nt][2], acc[nt][3]);
    }
}

// ---------------------------------------------------------------------------
extern "C" void kernel_launch(void* const* d_in, const int* in_sizes, int n_in,
                              void* d_out, int out_size) {
    const float* query = (const float*)d_in[0];
    const float* key   = (const float*)d_in[1];
    const float* value = (const float*)d_in[2];
    const int*   mask  = (const int*)d_in[3];
    const float* W1 = (const float*)d_in[4];
    const float* b1 = (const float*)d_in[5];
    const float* W2 = (const float*)d_in[6];
    const float* b2 = (const float*)d_in[7];
    const float* W3 = (const float*)d_in[8];
    const float* b3 = (const float*)d_in[9];

    float* out  = (float*)d_out;                 // [B, LQ, D]
    float* attn = out + (long)BB * LQ * DD;      // [B, LQ, LK]

    cudaFuncSetAttribute(proj_mma_kernel,
                         cudaFuncAttributeMaxDynamicSharedMemorySize, PM_SMEM);
    cudaFuncSetAttribute(score_mma_kernel,
                         cudaFuncAttributeMaxDynamicSharedMemorySize, SMEM_BYTES);
    cudaFuncSetAttribute(fused_softmax_av_kernel,
                         cudaFuncAttributeMaxDynamicSharedMemorySize, F_SMEM_BYTES);

    proj_mma_kernel<<<dim3(LQ / 16, BB, 3), 512, PM_SMEM>>>(query, key, W1, b1, W2);
    score_mma_kernel<<<SGRID, 512, SMEM_BYTES>>>(b2, W3, b3, attn);
    fused_softmax_av_kernel<<<dim3(LQ / 16, 2, BB), 256, F_SMEM_BYTES>>>(value, mask, out, attn);
}